// round 5
// baseline (speedup 1.0000x reference)
#include <cuda_runtime.h>
#include <math.h>
#include <float.h>

#define NPIL 60000
#define PPTS 32
#define SBLK 592   // k_stats block count (4 per SM)

// canonical per-block partial moment layout (65 floats):
// [0..3]   M1  = sum(u)               (u = masked x,y,z,w)
// [4..13]  M2  = sum(u u^T) upper-tri over 4
// [14..37] X   = sum(u_i * alpha_j)   (i in 0..3, j in 0..5; idx = 14 + i*6 + j)
// [38..58] A2  = sum(nv * alpha_a alpha_b) upper-tri over 6
// [59..64] A1  = sum(nv * alpha_j)
static __device__ float g_part[SBLK][65];
// per-channel folded params, 16 floats each (4 float4s)
static __device__ float g_params[64 * 16];
// per-pillar mean + center: [2i]={mx,my,mz,-}, [2i+1]={cx,cy,cz,-}
static __device__ float4 g_pm[NPIL * 2];

__global__ void __launch_bounds__(256) k_stats(const float4* __restrict__ pts,
                                               const int* __restrict__ nvs,
                                               const int4* __restrict__ coords) {
    __shared__ float sred[8 * 38];
    __shared__ float sown[8 * 27];
    const int lane = threadIdx.x & 31;
    const int warp = threadIdx.x >> 5;
    const int gw = blockIdx.x * 8 + warp;
    const int nw = SBLK * 8;

    // owned-entry (a6,b6) per lane: lanes 0..20 = upper-tri-6 pairs,
    // lanes 21..26 = A1 entries (b6 = 6 sentinel -> multiply by 1)
    int a6, b6;
    {
        int L = lane;
        if (L < 6)       { a6 = 0; b6 = L; }
        else if (L < 11) { a6 = 1; b6 = L - 5; }
        else if (L < 15) { a6 = 2; b6 = L - 9; }
        else if (L < 18) { a6 = 3; b6 = L - 12; }
        else if (L < 20) { a6 = 4; b6 = L - 14; }
        else if (L < 21) { a6 = 5; b6 = 5; }
        else             { a6 = L - 21; b6 = 6; }
    }
    const bool own_active = (lane < 27);

    float M1[4], M2[10], X[24];
#pragma unroll
    for (int k = 0; k < 4; k++)  M1[k] = 0.0f;
#pragma unroll
    for (int k = 0; k < 10; k++) M2[k] = 0.0f;
#pragma unroll
    for (int k = 0; k < 24; k++) X[k] = 0.0f;
    float own = 0.0f;

    for (int i = gw; i < NPIL; i += nw) {
        const float4 q = pts[i * PPTS + lane];
        const int nv = nvs[i];
        const int4 c = coords[i];

        // mean over ALL 32 points (reference sums unmasked, divides by nv)
        float sx = q.x, sy = q.y, sz = q.z;
#pragma unroll
        for (int s = 16; s > 0; s >>= 1) {
            sx += __shfl_xor_sync(0xffffffffu, sx, s);
            sy += __shfl_xor_sync(0xffffffffu, sy, s);
            sz += __shfl_xor_sync(0xffffffffu, sz, s);
        }
        const float inv = 1.0f / (float)nv;
        const float mx = sx * inv, my = sy * inv, mz = sz * inv;
        const float ccx = (float)c.w * 0.2f + 0.1f;
        const float ccy = (float)c.z * 0.2f - 39.9f;
        const float ccz = (float)c.y * 4.0f - 1.0f;
        if (lane == 0) {
            g_pm[2 * i]     = make_float4(mx, my, mz, 0.0f);
            g_pm[2 * i + 1] = make_float4(ccx, ccy, ccz, 0.0f);
        }

        const float valid = (lane < nv) ? 1.0f : 0.0f;
        const float ux = q.x * valid, uy = q.y * valid, uz = q.z * valid, uw = q.w * valid;

        M1[0] += ux; M1[1] += uy; M1[2] += uz; M1[3] += uw;
        M2[0] = fmaf(ux, ux, M2[0]); M2[1] = fmaf(ux, uy, M2[1]);
        M2[2] = fmaf(ux, uz, M2[2]); M2[3] = fmaf(ux, uw, M2[3]);
        M2[4] = fmaf(uy, uy, M2[4]); M2[5] = fmaf(uy, uz, M2[5]);
        M2[6] = fmaf(uy, uw, M2[6]); M2[7] = fmaf(uz, uz, M2[7]);
        M2[8] = fmaf(uz, uw, M2[8]); M2[9] = fmaf(uw, uw, M2[9]);

        // X[i*6+j] += u_i * alpha_j   (alpha = mx,my,mz,ccx,ccy,ccz)
        X[0]  = fmaf(ux, mx,  X[0]);  X[1]  = fmaf(ux, my,  X[1]);
        X[2]  = fmaf(ux, mz,  X[2]);  X[3]  = fmaf(ux, ccx, X[3]);
        X[4]  = fmaf(ux, ccy, X[4]);  X[5]  = fmaf(ux, ccz, X[5]);
        X[6]  = fmaf(uy, mx,  X[6]);  X[7]  = fmaf(uy, my,  X[7]);
        X[8]  = fmaf(uy, mz,  X[8]);  X[9]  = fmaf(uy, ccx, X[9]);
        X[10] = fmaf(uy, ccy, X[10]); X[11] = fmaf(uy, ccz, X[11]);
        X[12] = fmaf(uz, mx,  X[12]); X[13] = fmaf(uz, my,  X[13]);
        X[14] = fmaf(uz, mz,  X[14]); X[15] = fmaf(uz, ccx, X[15]);
        X[16] = fmaf(uz, ccy, X[16]); X[17] = fmaf(uz, ccz, X[17]);
        X[18] = fmaf(uw, mx,  X[18]); X[19] = fmaf(uw, my,  X[19]);
        X[20] = fmaf(uw, mz,  X[20]); X[21] = fmaf(uw, ccx, X[21]);
        X[22] = fmaf(uw, ccy, X[22]); X[23] = fmaf(uw, ccz, X[23]);

        // owned warp-uniform entry: nv * alpha_a6 * alpha_b6 (b6==6 -> *1)
        if (own_active) {
            const float va = (a6 == 0) ? mx : (a6 == 1) ? my : (a6 == 2) ? mz
                           : (a6 == 3) ? ccx : (a6 == 4) ? ccy : ccz;
            const float vb = (b6 >= 6) ? 1.0f
                           : (b6 == 0) ? mx : (b6 == 1) ? my : (b6 == 2) ? mz
                           : (b6 == 3) ? ccx : (b6 == 4) ? ccy : ccz;
            own = fmaf((float)nv, va * vb, own);
        }
    }

    // reduce the 38 per-lane accumulators across the warp
#pragma unroll
    for (int k = 0; k < 4; k++) {
        float v = M1[k];
#pragma unroll
        for (int s = 16; s > 0; s >>= 1) v += __shfl_xor_sync(0xffffffffu, v, s);
        if (lane == 0) sred[warp * 38 + k] = v;
    }
#pragma unroll
    for (int k = 0; k < 10; k++) {
        float v = M2[k];
#pragma unroll
        for (int s = 16; s > 0; s >>= 1) v += __shfl_xor_sync(0xffffffffu, v, s);
        if (lane == 0) sred[warp * 38 + 4 + k] = v;
    }
#pragma unroll
    for (int k = 0; k < 24; k++) {
        float v = X[k];
#pragma unroll
        for (int s = 16; s > 0; s >>= 1) v += __shfl_xor_sync(0xffffffffu, v, s);
        if (lane == 0) sred[warp * 38 + 14 + k] = v;
    }
    if (own_active) sown[warp * 27 + lane] = own;
    __syncthreads();

    const int t = threadIdx.x;
    if (t < 65) {
        float s = 0.0f;
#pragma unroll
        for (int w = 0; w < 8; w++)
            s += (t < 38) ? sred[w * 38 + t] : sown[w * 27 + (t - 38)];
        g_part[blockIdx.x][t] = s;
    }
}

__global__ void __launch_bounds__(128) k_bn(const float* __restrict__ W,
                                            const float* __restrict__ gamma,
                                            const float* __restrict__ beta) {
    __shared__ float s_acc[65];
    const int t = threadIdx.x;
    if (t < 65) {
        float s0 = 0, s1 = 0, s2 = 0, s3 = 0, s4 = 0, s5 = 0, s6 = 0, s7 = 0;
        for (int b = 0; b < SBLK; b += 8) {   // SBLK = 592 = 8*74
            s0 += g_part[b + 0][t]; s1 += g_part[b + 1][t];
            s2 += g_part[b + 2][t]; s3 += g_part[b + 3][t];
            s4 += g_part[b + 4][t]; s5 += g_part[b + 5][t];
            s6 += g_part[b + 6][t]; s7 += g_part[b + 7][t];
        }
        s_acc[t] = ((s0 + s1) + (s2 + s3)) + ((s4 + s5) + (s6 + s7));
    }
    __syncthreads();
    if (t >= 64) return;
    const int o = t;

    const int pidx[10] = {0, 1, 2, 3, 0, 1, 2, 0, 1, 2};
    const int aidx[10] = {-1, -1, -1, -1, 0, 1, 2, 3, 4, 5};

    double w[10];
#pragma unroll
    for (int cc = 0; cc < 10; cc++) w[cc] = (double)W[o * 10 + cc];
    const double NP = (double)NPIL * (double)PPTS;

    double mean = 0.0;
#pragma unroll
    for (int a = 0; a < 10; a++) {
        double g1 = (double)s_acc[pidx[a]];
        if (aidx[a] >= 0) g1 -= (double)s_acc[59 + aidx[a]];
        mean += w[a] * g1;
    }
    mean /= NP;

    double e2 = 0.0;
#pragma unroll
    for (int a = 0; a < 10; a++) {
#pragma unroll
        for (int b = 0; b < 10; b++) {
            if (b < a) continue;
            const int pa = pidx[a], pb = pidx[b];
            const int i4 = (pa <= pb) ? pa : pb;
            const int j4 = (pa <= pb) ? pb : pa;
            double g2 = (double)s_acc[4 + (i4 * 4 - i4 * (i4 - 1) / 2 + (j4 - i4))];
            if (aidx[a] >= 0) g2 -= (double)s_acc[14 + pb * 6 + aidx[a]];
            if (aidx[b] >= 0) g2 -= (double)s_acc[14 + pa * 6 + aidx[b]];
            if (aidx[a] >= 0 && aidx[b] >= 0) {
                const int i6 = (aidx[a] <= aidx[b]) ? aidx[a] : aidx[b];
                const int j6 = (aidx[a] <= aidx[b]) ? aidx[b] : aidx[a];
                g2 += (double)s_acc[38 + (i6 * 6 - i6 * (i6 - 1) / 2 + (j6 - i6))];
            }
            e2 += w[a] * w[b] * g2 * ((a == b) ? 1.0 : 2.0);
        }
    }
    e2 /= NP;

    const double var = e2 - mean * mean;
    const double aa = (double)gamma[o] / sqrt(var + 1e-3);
    const double bb = (double)beta[o] - mean * aa;
    float* p = g_params + o * 16;
    p[0]  = (float)(aa * (w[0] + w[4] + w[7]));
    p[1]  = (float)(aa * (w[1] + w[5] + w[8]));
    p[2]  = (float)(aa * (w[2] + w[6] + w[9]));
    p[3]  = (float)(aa * w[3]);
    p[4]  = (float)(aa * w[4]);
    p[5]  = (float)(aa * w[5]);
    p[6]  = (float)(aa * w[6]);
    p[7]  = (float)(aa * w[7]);
    p[8]  = (float)(aa * w[8]);
    p[9]  = (float)(aa * w[9]);
    p[10] = (float)bb;
    p[11] = 0.0f;
    p[12] = 0.0f; p[13] = 0.0f; p[14] = 0.0f; p[15] = 0.0f;
}

// Output kernel: warp = pillar (grid-stride), params staged in shared,
// 4-wide unroll with 8 independent max accumulators.
// max_p(pb + d_p) == pb + max_p(d_p).
__global__ void __launch_bounds__(256) k_out(const float4* __restrict__ pts,
                                             const int* __restrict__ nvs,
                                             float* __restrict__ out) {
    __shared__ float4 sp[8][32];
    __shared__ float4 s_par[64 * 4];
    const int lane = threadIdx.x & 31;
    const int warp = threadIdx.x >> 5;

    s_par[threadIdx.x] = ((const float4*)g_params)[threadIdx.x];
    __syncthreads();

    const float4 wc0 = s_par[lane * 4 + 0];
    const float4 wc1 = s_par[(lane + 32) * 4 + 0];

    const int gw = blockIdx.x * 8 + warp;
    const int nw = gridDim.x * 8;

    for (int i = gw; i < NPIL; i += nw) {
        const float4 q = pts[i * PPTS + lane];
        sp[warp][lane] = q;
        const int nv = nvs[i];
        __syncwarp();

        const float4 pm = g_pm[2 * i];
        const float4 pc = g_pm[2 * i + 1];
        const float4 c0m = s_par[lane * 4 + 1];
        const float4 c0t = s_par[lane * 4 + 2];
        const float4 c1m = s_par[(lane + 32) * 4 + 1];
        const float4 c1t = s_par[(lane + 32) * 4 + 2];
        const float pb0 = c0t.z - (pm.x * c0m.x + pm.y * c0m.y + pm.z * c0m.z)
                                - (pc.x * c0m.w + pc.y * c0t.x + pc.z * c0t.y);
        const float pb1 = c1t.z - (pm.x * c1m.x + pm.y * c1m.y + pm.z * c1m.z)
                                - (pc.x * c1m.w + pc.y * c1t.x + pc.z * c1t.y);

        const float4* s4 = sp[warp];
        float m0 = -FLT_MAX, m1 = -FLT_MAX, m2 = -FLT_MAX, m3 = -FLT_MAX;
        float n0 = -FLT_MAX, n1 = -FLT_MAX, n2 = -FLT_MAX, n3 = -FLT_MAX;
        int p = 0;
        for (; p + 4 <= nv; p += 4) {
            const float4 r0 = s4[p];
            const float4 r1 = s4[p + 1];
            const float4 r2 = s4[p + 2];
            const float4 r3 = s4[p + 3];
            m0 = fmaxf(m0, fmaf(r0.x, wc0.x, fmaf(r0.y, wc0.y, fmaf(r0.z, wc0.z, r0.w * wc0.w))));
            m1 = fmaxf(m1, fmaf(r1.x, wc0.x, fmaf(r1.y, wc0.y, fmaf(r1.z, wc0.z, r1.w * wc0.w))));
            m2 = fmaxf(m2, fmaf(r2.x, wc0.x, fmaf(r2.y, wc0.y, fmaf(r2.z, wc0.z, r2.w * wc0.w))));
            m3 = fmaxf(m3, fmaf(r3.x, wc0.x, fmaf(r3.y, wc0.y, fmaf(r3.z, wc0.z, r3.w * wc0.w))));
            n0 = fmaxf(n0, fmaf(r0.x, wc1.x, fmaf(r0.y, wc1.y, fmaf(r0.z, wc1.z, r0.w * wc1.w))));
            n1 = fmaxf(n1, fmaf(r1.x, wc1.x, fmaf(r1.y, wc1.y, fmaf(r1.z, wc1.z, r1.w * wc1.w))));
            n2 = fmaxf(n2, fmaf(r2.x, wc1.x, fmaf(r2.y, wc1.y, fmaf(r2.z, wc1.z, r2.w * wc1.w))));
            n3 = fmaxf(n3, fmaf(r3.x, wc1.x, fmaf(r3.y, wc1.y, fmaf(r3.z, wc1.z, r3.w * wc1.w))));
        }
        for (; p < nv; p++) {
            const float4 r0 = s4[p];
            m0 = fmaxf(m0, fmaf(r0.x, wc0.x, fmaf(r0.y, wc0.y, fmaf(r0.z, wc0.z, r0.w * wc0.w))));
            n0 = fmaxf(n0, fmaf(r0.x, wc1.x, fmaf(r0.y, wc1.y, fmaf(r0.z, wc1.z, r0.w * wc1.w))));
        }
        __syncwarp();

        float r0 = pb0 + fmaxf(fmaxf(m0, m1), fmaxf(m2, m3));
        float r1 = pb1 + fmaxf(fmaxf(n0, n1), fmaxf(n2, n3));
        if (nv < PPTS) {   // masked points contribute exactly b pre-ReLU
            r0 = fmaxf(r0, c0t.z);
            r1 = fmaxf(r1, c1t.z);
        }
        out[i * 64 + lane]      = fmaxf(r0, 0.0f);
        out[i * 64 + 32 + lane] = fmaxf(r1, 0.0f);
    }
}

extern "C" void kernel_launch(void* const* d_in, const int* in_sizes, int n_in,
                              void* d_out, int out_size) {
    const float4* feats  = (const float4*)d_in[0];
    const int*    nvs    = (const int*)d_in[1];
    const int4*   coords = (const int4*)d_in[2];
    const float*  W      = (const float*)d_in[3];
    const float*  gamma  = (const float*)d_in[4];
    const float*  beta   = (const float*)d_in[5];
    float* out = (float*)d_out;

    k_stats<<<SBLK, 256>>>(feats, nvs, coords);
    k_bn<<<1, 128>>>(W, gamma, beta);
    k_out<<<1184, 256>>>(feats, nvs, out);
}

// round 6
// speedup vs baseline: 1.0276x; 1.0276x over previous
#include <cuda_runtime.h>
#include <math.h>
#include <float.h>

#define NPIL 60000
#define PPTS 32
#define PMBLK 1184   // k_pm block count
#define SBLK  592    // k_stats block count

// pillar-level A-moment partials from k_pm: [0..20]=A2 tri6, [21..26]=A1
static __device__ float g_partA[PMBLK][27];
// point-level moment partials from k_stats:
// [0..3]=M1=sum(u), [4..13]=M2 tri4, [14..37]=X[i*6+j]=sum(u_i*alpha_j)
static __device__ float g_part[SBLK][38];
// per-channel folded params, 16 floats each (4 float4s)
static __device__ float g_params[64 * 16];
// per-pillar mean + center: [2i]={mx,my,mz,-}, [2i+1]={cx,cy,cz,-}
static __device__ float4 g_pm[NPIL * 2];

// ---------------------------------------------------------------------------
// k_pm: warp per pillar. Computes pillar mean (butterfly over all 32 pts,
// reference divides by nv) + voxel center, stores g_pm. Also accumulates the
// 27 pillar-level alpha moments (A2 = nv*alpha_a*alpha_b tri6, A1 = nv*alpha_j)
// via lane ownership. All shuffle work concentrated here (low regs, high occ).
// ---------------------------------------------------------------------------
__global__ void __launch_bounds__(256) k_pm(const float4* __restrict__ pts,
                                            const int* __restrict__ nvs,
                                            const int4* __restrict__ coords) {
    __shared__ float sA[8][27];
    const int lane = threadIdx.x & 31;
    const int warp = threadIdx.x >> 5;
    const int gw = blockIdx.x * 8 + warp;
    const int nw = PMBLK * 8;

    // owned-entry (a6,b6): lanes 0..20 = upper-tri-6 pairs, 21..26 = A1 (b6=6 -> *1)
    int a6, b6;
    {
        const int L = lane;
        if (L < 6)       { a6 = 0; b6 = L; }
        else if (L < 11) { a6 = 1; b6 = L - 5; }
        else if (L < 15) { a6 = 2; b6 = L - 9; }
        else if (L < 18) { a6 = 3; b6 = L - 12; }
        else if (L < 20) { a6 = 4; b6 = L - 14; }
        else if (L < 21) { a6 = 5; b6 = 5; }
        else             { a6 = L - 21; b6 = 6; }
    }
    const bool own_active = (lane < 27);

    float own = 0.0f;
    for (int i = gw; i < NPIL; i += nw) {
        const float4 q = pts[i * PPTS + lane];
        const int nv = nvs[i];
        const int4 c = coords[i];

        float sx = q.x, sy = q.y, sz = q.z;
#pragma unroll
        for (int s = 16; s > 0; s >>= 1) {
            sx += __shfl_xor_sync(0xffffffffu, sx, s);
            sy += __shfl_xor_sync(0xffffffffu, sy, s);
            sz += __shfl_xor_sync(0xffffffffu, sz, s);
        }
        const float inv = 1.0f / (float)nv;
        const float mx = sx * inv, my = sy * inv, mz = sz * inv;
        const float ccx = (float)c.w * 0.2f + 0.1f;
        const float ccy = (float)c.z * 0.2f - 39.9f;
        const float ccz = (float)c.y * 4.0f - 1.0f;
        if (lane == 0) {
            g_pm[2 * i]     = make_float4(mx, my, mz, 0.0f);
            g_pm[2 * i + 1] = make_float4(ccx, ccy, ccz, 0.0f);
        }
        if (own_active) {
            const float va = (a6 == 0) ? mx : (a6 == 1) ? my : (a6 == 2) ? mz
                           : (a6 == 3) ? ccx : (a6 == 4) ? ccy : ccz;
            const float vb = (b6 >= 6) ? 1.0f
                           : (b6 == 0) ? mx : (b6 == 1) ? my : (b6 == 2) ? mz
                           : (b6 == 3) ? ccx : (b6 == 4) ? ccy : ccz;
            own = fmaf((float)nv, va * vb, own);
        }
    }

    if (own_active) sA[warp][lane] = own;
    __syncthreads();
    const int t = threadIdx.x;
    if (t < 27) {
        float s = 0.0f;
#pragma unroll
        for (int w = 0; w < 8; w++) s += sA[w][t];
        g_partA[blockIdx.x][t] = s;
    }
}

// ---------------------------------------------------------------------------
// k_stats: point-level moments, NO shuffles, NO selects. Streams q + g_pm
// (warp-uniform broadcast loads). 38 independent FMAs per pillar per lane.
// ---------------------------------------------------------------------------
__global__ void __launch_bounds__(256) k_stats(const float4* __restrict__ pts,
                                               const int* __restrict__ nvs) {
    __shared__ float sred[8][38];
    const int lane = threadIdx.x & 31;
    const int warp = threadIdx.x >> 5;
    const int gw = blockIdx.x * 8 + warp;
    const int nw = SBLK * 8;

    float M1[4], M2[10], X[24];
#pragma unroll
    for (int k = 0; k < 4; k++)  M1[k] = 0.0f;
#pragma unroll
    for (int k = 0; k < 10; k++) M2[k] = 0.0f;
#pragma unroll
    for (int k = 0; k < 24; k++) X[k] = 0.0f;

    for (int i = gw; i < NPIL; i += nw) {
        const float4 q = pts[i * PPTS + lane];
        const int nv = nvs[i];
        const float4 al0 = g_pm[2 * i];       // mx,my,mz
        const float4 al1 = g_pm[2 * i + 1];   // cx,cy,cz

        const float valid = (lane < nv) ? 1.0f : 0.0f;
        const float ux = q.x * valid, uy = q.y * valid, uz = q.z * valid, uw = q.w * valid;

        M1[0] += ux; M1[1] += uy; M1[2] += uz; M1[3] += uw;
        M2[0] = fmaf(ux, ux, M2[0]); M2[1] = fmaf(ux, uy, M2[1]);
        M2[2] = fmaf(ux, uz, M2[2]); M2[3] = fmaf(ux, uw, M2[3]);
        M2[4] = fmaf(uy, uy, M2[4]); M2[5] = fmaf(uy, uz, M2[5]);
        M2[6] = fmaf(uy, uw, M2[6]); M2[7] = fmaf(uz, uz, M2[7]);
        M2[8] = fmaf(uz, uw, M2[8]); M2[9] = fmaf(uw, uw, M2[9]);

        X[0]  = fmaf(ux, al0.x, X[0]);  X[1]  = fmaf(ux, al0.y, X[1]);
        X[2]  = fmaf(ux, al0.z, X[2]);  X[3]  = fmaf(ux, al1.x, X[3]);
        X[4]  = fmaf(ux, al1.y, X[4]);  X[5]  = fmaf(ux, al1.z, X[5]);
        X[6]  = fmaf(uy, al0.x, X[6]);  X[7]  = fmaf(uy, al0.y, X[7]);
        X[8]  = fmaf(uy, al0.z, X[8]);  X[9]  = fmaf(uy, al1.x, X[9]);
        X[10] = fmaf(uy, al1.y, X[10]); X[11] = fmaf(uy, al1.z, X[11]);
        X[12] = fmaf(uz, al0.x, X[12]); X[13] = fmaf(uz, al0.y, X[13]);
        X[14] = fmaf(uz, al0.z, X[14]); X[15] = fmaf(uz, al1.x, X[15]);
        X[16] = fmaf(uz, al1.y, X[16]); X[17] = fmaf(uz, al1.z, X[17]);
        X[18] = fmaf(uw, al0.x, X[18]); X[19] = fmaf(uw, al0.y, X[19]);
        X[20] = fmaf(uw, al0.z, X[20]); X[21] = fmaf(uw, al1.x, X[21]);
        X[22] = fmaf(uw, al1.y, X[22]); X[23] = fmaf(uw, al1.z, X[23]);
    }

    // warp butterfly reduce all 38, lane0 stages, block sums -> per-block partial
#pragma unroll
    for (int k = 0; k < 4; k++) {
        float v = M1[k];
#pragma unroll
        for (int s = 16; s > 0; s >>= 1) v += __shfl_xor_sync(0xffffffffu, v, s);
        if (lane == 0) sred[warp][k] = v;
    }
#pragma unroll
    for (int k = 0; k < 10; k++) {
        float v = M2[k];
#pragma unroll
        for (int s = 16; s > 0; s >>= 1) v += __shfl_xor_sync(0xffffffffu, v, s);
        if (lane == 0) sred[warp][4 + k] = v;
    }
#pragma unroll
    for (int k = 0; k < 24; k++) {
        float v = X[k];
#pragma unroll
        for (int s = 16; s > 0; s >>= 1) v += __shfl_xor_sync(0xffffffffu, v, s);
        if (lane == 0) sred[warp][14 + k] = v;
    }
    __syncthreads();
    const int t = threadIdx.x;
    if (t < 38) {
        float s = 0.0f;
#pragma unroll
        for (int w = 0; w < 8; w++) s += sred[w][t];
        g_part[blockIdx.x][t] = s;
    }
}

// ---------------------------------------------------------------------------
// k_bn: reduce partials, reconstruct exact 10x10 feature moments, derive
// per-channel BN-folded params (double precision for safety).
// s_acc layout: [0..3]=M1, [4..13]=M2 tri4, [14..37]=X, [38..58]=A2, [59..64]=A1
// ---------------------------------------------------------------------------
__global__ void __launch_bounds__(128) k_bn(const float* __restrict__ W,
                                            const float* __restrict__ gamma,
                                            const float* __restrict__ beta) {
    __shared__ float s_acc[65];
    const int t = threadIdx.x;
    if (t < 38) {
        float s0 = 0, s1 = 0, s2 = 0, s3 = 0, s4 = 0, s5 = 0, s6 = 0, s7 = 0;
        for (int b = 0; b < SBLK; b += 8) {   // 592 = 8*74
            s0 += g_part[b + 0][t]; s1 += g_part[b + 1][t];
            s2 += g_part[b + 2][t]; s3 += g_part[b + 3][t];
            s4 += g_part[b + 4][t]; s5 += g_part[b + 5][t];
            s6 += g_part[b + 6][t]; s7 += g_part[b + 7][t];
        }
        s_acc[t] = ((s0 + s1) + (s2 + s3)) + ((s4 + s5) + (s6 + s7));
    } else if (t < 65) {
        const int k = t - 38;
        float s0 = 0, s1 = 0, s2 = 0, s3 = 0, s4 = 0, s5 = 0, s6 = 0, s7 = 0;
        for (int b = 0; b < PMBLK; b += 8) {  // 1184 = 8*148
            s0 += g_partA[b + 0][k]; s1 += g_partA[b + 1][k];
            s2 += g_partA[b + 2][k]; s3 += g_partA[b + 3][k];
            s4 += g_partA[b + 4][k]; s5 += g_partA[b + 5][k];
            s6 += g_partA[b + 6][k]; s7 += g_partA[b + 7][k];
        }
        s_acc[t] = ((s0 + s1) + (s2 + s3)) + ((s4 + s5) + (s6 + s7));
    }
    __syncthreads();
    if (t >= 64) return;
    const int o = t;

    const int pidx[10] = {0, 1, 2, 3, 0, 1, 2, 0, 1, 2};
    const int aidx[10] = {-1, -1, -1, -1, 0, 1, 2, 3, 4, 5};

    double w[10];
#pragma unroll
    for (int cc = 0; cc < 10; cc++) w[cc] = (double)W[o * 10 + cc];
    const double NP = (double)NPIL * (double)PPTS;

    double mean = 0.0;
#pragma unroll
    for (int a = 0; a < 10; a++) {
        double g1 = (double)s_acc[pidx[a]];
        if (aidx[a] >= 0) g1 -= (double)s_acc[59 + aidx[a]];
        mean += w[a] * g1;
    }
    mean /= NP;

    double e2 = 0.0;
#pragma unroll
    for (int a = 0; a < 10; a++) {
#pragma unroll
        for (int b = 0; b < 10; b++) {
            if (b < a) continue;
            const int pa = pidx[a], pb = pidx[b];
            const int i4 = (pa <= pb) ? pa : pb;
            const int j4 = (pa <= pb) ? pb : pa;
            double g2 = (double)s_acc[4 + (i4 * 4 - i4 * (i4 - 1) / 2 + (j4 - i4))];
            if (aidx[a] >= 0) g2 -= (double)s_acc[14 + pb * 6 + aidx[a]];
            if (aidx[b] >= 0) g2 -= (double)s_acc[14 + pa * 6 + aidx[b]];
            if (aidx[a] >= 0 && aidx[b] >= 0) {
                const int i6 = (aidx[a] <= aidx[b]) ? aidx[a] : aidx[b];
                const int j6 = (aidx[a] <= aidx[b]) ? aidx[b] : aidx[a];
                g2 += (double)s_acc[38 + (i6 * 6 - i6 * (i6 - 1) / 2 + (j6 - i6))];
            }
            e2 += w[a] * w[b] * g2 * ((a == b) ? 1.0 : 2.0);
        }
    }
    e2 /= NP;

    const double var = e2 - mean * mean;
    const double aa = (double)gamma[o] / sqrt(var + 1e-3);
    const double bb = (double)beta[o] - mean * aa;
    float* p = g_params + o * 16;
    p[0]  = (float)(aa * (w[0] + w[4] + w[7]));
    p[1]  = (float)(aa * (w[1] + w[5] + w[8]));
    p[2]  = (float)(aa * (w[2] + w[6] + w[9]));
    p[3]  = (float)(aa * w[3]);
    p[4]  = (float)(aa * w[4]);
    p[5]  = (float)(aa * w[5]);
    p[6]  = (float)(aa * w[6]);
    p[7]  = (float)(aa * w[7]);
    p[8]  = (float)(aa * w[8]);
    p[9]  = (float)(aa * w[9]);
    p[10] = (float)bb;
    p[11] = 0.0f;
    p[12] = 0.0f; p[13] = 0.0f; p[14] = 0.0f; p[15] = 0.0f;
}

// ---------------------------------------------------------------------------
// k_out: R1-proven structure (params in registers, warp=pillar, nv-bounded
// loop over shared tile, 2 channels per lane) with the shuffle chain replaced
// by two warp-uniform g_pm loads. max_p(pb + d_p) == pb + max_p(d_p).
// ---------------------------------------------------------------------------
__global__ void __launch_bounds__(256) k_out(const float4* __restrict__ pts,
                                             const int* __restrict__ nvs,
                                             float* __restrict__ out) {
    __shared__ float4 sp[8][32];
    const int lane = threadIdx.x & 31;
    const int warp = threadIdx.x >> 5;
    const int gw = blockIdx.x * 8 + warp;
    const int nw = gridDim.x * 8;

    const float4* pp = (const float4*)g_params;
    const float4 wc0 = pp[lane * 4 + 0];
    const float4 m0v = pp[lane * 4 + 1];          // {aW4,aW5,aW6,aW7}
    const float4 t0v = pp[lane * 4 + 2];          // {aW8,aW9,b,pad}
    const float4 wc1 = pp[(lane + 32) * 4 + 0];
    const float4 m1v = pp[(lane + 32) * 4 + 1];
    const float4 t1v = pp[(lane + 32) * 4 + 2];

    for (int i = gw; i < NPIL; i += nw) {
        const float4 q = pts[i * PPTS + lane];
        sp[warp][lane] = q;
        const int nv = nvs[i];
        const float4 pm = g_pm[2 * i];
        const float4 pc = g_pm[2 * i + 1];
        __syncwarp();

        const float pb0 = t0v.z - (pm.x * m0v.x + pm.y * m0v.y + pm.z * m0v.z)
                                - (pc.x * m0v.w + pc.y * t0v.x + pc.z * t0v.y);
        const float pb1 = t1v.z - (pm.x * m1v.x + pm.y * m1v.y + pm.z * m1v.z)
                                - (pc.x * m1v.w + pc.y * t1v.x + pc.z * t1v.y);

        const float4* s4 = sp[warp];
        float a0 = -FLT_MAX, b0 = -FLT_MAX, a1 = -FLT_MAX, b1 = -FLT_MAX;
        int p = 0;
        for (; p + 2 <= nv; p += 2) {
            const float4 r0 = s4[p];
            const float4 r1 = s4[p + 1];
            a0 = fmaxf(a0, fmaf(r0.x, wc0.x, fmaf(r0.y, wc0.y, fmaf(r0.z, wc0.z, r0.w * wc0.w))));
            b0 = fmaxf(b0, fmaf(r1.x, wc0.x, fmaf(r1.y, wc0.y, fmaf(r1.z, wc0.z, r1.w * wc0.w))));
            a1 = fmaxf(a1, fmaf(r0.x, wc1.x, fmaf(r0.y, wc1.y, fmaf(r0.z, wc1.z, r0.w * wc1.w))));
            b1 = fmaxf(b1, fmaf(r1.x, wc1.x, fmaf(r1.y, wc1.y, fmaf(r1.z, wc1.z, r1.w * wc1.w))));
        }
        if (p < nv) {
            const float4 r0 = s4[p];
            a0 = fmaxf(a0, fmaf(r0.x, wc0.x, fmaf(r0.y, wc0.y, fmaf(r0.z, wc0.z, r0.w * wc0.w))));
            a1 = fmaxf(a1, fmaf(r0.x, wc1.x, fmaf(r0.y, wc1.y, fmaf(r0.z, wc1.z, r0.w * wc1.w))));
        }
        __syncwarp();

        float r0 = pb0 + fmaxf(a0, b0);
        float r1 = pb1 + fmaxf(a1, b1);
        if (nv < PPTS) {   // masked points contribute exactly b pre-ReLU
            r0 = fmaxf(r0, t0v.z);
            r1 = fmaxf(r1, t1v.z);
        }
        out[i * 64 + lane]      = fmaxf(r0, 0.0f);
        out[i * 64 + 32 + lane] = fmaxf(r1, 0.0f);
    }
}

extern "C" void kernel_launch(void* const* d_in, const int* in_sizes, int n_in,
                              void* d_out, int out_size) {
    const float4* feats  = (const float4*)d_in[0];
    const int*    nvs    = (const int*)d_in[1];
    const int4*   coords = (const int4*)d_in[2];
    const float*  W      = (const float*)d_in[3];
    const float*  gamma  = (const float*)d_in[4];
    const float*  beta   = (const float*)d_in[5];
    float* out = (float*)d_out;

    k_pm<<<PMBLK, 256>>>(feats, nvs, coords);
    k_stats<<<SBLK, 256>>>(feats, nvs);
    k_bn<<<1, 128>>>(W, gamma, beta);
    k_out<<<1184, 256>>>(feats, nvs, out);
}

// round 8
// speedup vs baseline: 1.2771x; 1.2428x over previous
#include <cuda_runtime.h>
#include <math.h>
#include <float.h>

#define NPIL 60000
#define PPTS 32
#define SBLK 296

// moment partials, entry-major for coalesced reduction:
// entry t: [0..3]=M1(sum u), [4..13]=M2 tri4, [14..37]=X[i*6+j]=sum(u_i*alpha_j),
//          [38..58]=A2 tri6 (nv*alpha_a*alpha_b), [59..64]=A1 (nv*alpha_j)
static __device__ float g_part[65][SBLK];
// per-channel folded params, 16 floats each (4 float4s)
static __device__ float g_params[64 * 16];
// per-pillar mean + center: [2i]={mx,my,mz,-}, [2i+1]={cx,cy,cz,-}
static __device__ float4 g_pm[NPIL * 2];

// owned-entry space e in [0,55): e<4 -> M1[e]; e<28 -> X[e-4]; e<49 -> A2[e-28]; else A1[e-49]
// operand table index: 0..5 = alpha (mx,my,mz,cx,cy,cz), 6..9 = S (masked sum of u), 10 = 1.0
__device__ __forceinline__ void decode_entry(int e, int& ia, int& ib, int& use_nv) {
    if (e < 4)       { ia = 6 + e; ib = 10; use_nv = 0; }
    else if (e < 28) { const int k = e - 4; ia = 6 + k / 6; ib = k % 6; use_nv = 0; }
    else if (e < 49) { int k = e - 28; int a = 0;
                       while (k >= 6 - a) { k -= 6 - a; a++; }
                       ia = a; ib = a + k; use_nv = 1; }
    else             { ia = e - 49; ib = 10; use_nv = 1; }
}

// ---------------------------------------------------------------------------
// k_stats: ONE pass over pts. Per-lane accumulators: M2 only (10).
// M1/X/A2/A1 are warp-uniform per pillar -> lane-owned (2 entries per lane)
// via a shared 11-operand table. Also computes and stores g_pm.
// ---------------------------------------------------------------------------
__global__ void __launch_bounds__(256) k_stats(const float4* __restrict__ pts,
                                               const int* __restrict__ nvs,
                                               const int4* __restrict__ coords) {
    __shared__ float sT[8][12];    // operand table per warp (11 used)
    __shared__ float sM2[8][10];
    __shared__ float sE[8][55];
    const int lane = threadIdx.x & 31;
    const int warp = threadIdx.x >> 5;
    const int gw = blockIdx.x * 8 + warp;
    const int nw = SBLK * 8;

    int iaA, ibA, unvA; decode_entry(lane, iaA, ibA, unvA);
    int iaB = 0, ibB = 10, unvB = 0;
    const bool hasB = (lane < 23);                 // entries 32..54
    if (hasB) decode_entry(lane + 32, iaB, ibB, unvB);

    float M2[10];
#pragma unroll
    for (int k = 0; k < 10; k++) M2[k] = 0.0f;
    float accA = 0.0f, accB = 0.0f;

    int i = gw;                                    // gw < 2368 <= NPIL always
    float4 q = pts[i * PPTS + lane];
    int nv = nvs[i];
    int4 c = coords[i];

    for (;;) {
        const int inext = i + nw;
        const bool more = inext < NPIL;
        float4 qn; int nvn = 0; int4 cn;
        if (more) {                                // prefetch next pillar
            qn = pts[inext * PPTS + lane];
            nvn = nvs[inext];
            cn = coords[inext];
        }

        // unmasked xyz sum (reference sums all 32 points, divides by nv)
        float sx = q.x, sy = q.y, sz = q.z;
#pragma unroll
        for (int s = 16; s > 0; s >>= 1) {
            sx += __shfl_xor_sync(0xffffffffu, sx, s);
            sy += __shfl_xor_sync(0xffffffffu, sy, s);
            sz += __shfl_xor_sync(0xffffffffu, sz, s);
        }
        const float inv = 1.0f / (float)nv;
        const float mx = sx * inv, my = sy * inv, mz = sz * inv;
        const float cx = (float)c.w * 0.2f + 0.1f;
        const float cy = (float)c.z * 0.2f - 39.9f;
        const float cz = (float)c.y * 4.0f - 1.0f;
        if (lane == 0) {
            g_pm[2 * i]     = make_float4(mx, my, mz, 0.0f);
            g_pm[2 * i + 1] = make_float4(cx, cy, cz, 0.0f);
        }

        // masked u + masked 4-dim pillar sum S
        const float valid = (lane < nv) ? 1.0f : 0.0f;
        const float ux = q.x * valid, uy = q.y * valid, uz = q.z * valid, uw = q.w * valid;
        float Sx = ux, Sy = uy, Sz = uz, Sw = uw;
#pragma unroll
        for (int s = 16; s > 0; s >>= 1) {
            Sx += __shfl_xor_sync(0xffffffffu, Sx, s);
            Sy += __shfl_xor_sync(0xffffffffu, Sy, s);
            Sz += __shfl_xor_sync(0xffffffffu, Sz, s);
            Sw += __shfl_xor_sync(0xffffffffu, Sw, s);
        }

        // stage operand table {alpha(6), S(4), 1}
        float sv = 1.0f;
        if (lane == 0) sv = mx; else if (lane == 1) sv = my; else if (lane == 2) sv = mz;
        else if (lane == 3) sv = cx; else if (lane == 4) sv = cy; else if (lane == 5) sv = cz;
        else if (lane == 6) sv = Sx; else if (lane == 7) sv = Sy;
        else if (lane == 8) sv = Sz; else if (lane == 9) sv = Sw;
        if (lane < 11) sT[warp][lane] = sv;
        __syncwarp();

        const float nvf = (float)nv;
        {
            const float va = sT[warp][iaA];
            const float vb = sT[warp][ibA];
            accA = fmaf(va * vb, unvA ? nvf : 1.0f, accA);
        }
        if (hasB) {
            const float va = sT[warp][iaB];
            const float vb = sT[warp][ibB];
            accB = fmaf(va * vb, unvB ? nvf : 1.0f, accB);
        }
        __syncwarp();   // table reads complete before next pillar overwrites

        // M2 (per-lane point-level) — independent of the table
        M2[0] = fmaf(ux, ux, M2[0]); M2[1] = fmaf(ux, uy, M2[1]);
        M2[2] = fmaf(ux, uz, M2[2]); M2[3] = fmaf(ux, uw, M2[3]);
        M2[4] = fmaf(uy, uy, M2[4]); M2[5] = fmaf(uy, uz, M2[5]);
        M2[6] = fmaf(uy, uw, M2[6]); M2[7] = fmaf(uz, uz, M2[7]);
        M2[8] = fmaf(uz, uw, M2[8]); M2[9] = fmaf(uw, uw, M2[9]);

        if (!more) break;
        i = inext; q = qn; nv = nvn; c = cn;
    }

    // epilogue: reduce M2 across the warp, stage owned entries, block-reduce
#pragma unroll
    for (int k = 0; k < 10; k++) {
        float v = M2[k];
#pragma unroll
        for (int s = 16; s > 0; s >>= 1) v += __shfl_xor_sync(0xffffffffu, v, s);
        if (lane == 0) sM2[warp][k] = v;
    }
    sE[warp][lane < 32 ? lane : 0] = accA;   // entries 0..31 (lane<32 always true)
    if (hasB) sE[warp][lane + 32] = accB;    // entries 32..54
    __syncthreads();

    const int t = threadIdx.x;
    if (t < 65) {
        float s = 0.0f;
#pragma unroll
        for (int w = 0; w < 8; w++) {
            if (t < 4)       s += sE[w][t];        // M1
            else if (t < 14) s += sM2[w][t - 4];   // M2
            else             s += sE[w][t - 10];   // X / A2 / A1
        }
        g_part[t][blockIdx.x] = s;
    }
}

// ---------------------------------------------------------------------------
// k_bn: parallel reduce of g_part (8 threads per entry), then per-channel
// BN-folded param derivation in double precision.
// ---------------------------------------------------------------------------
__global__ void __launch_bounds__(544) k_bn(const float* __restrict__ W,
                                            const float* __restrict__ gamma,
                                            const float* __restrict__ beta) {
    __shared__ float sp8[65][8];
    __shared__ float s_acc[65];
    const int t = threadIdx.x;
    if (t < 520) {
        const int e = t >> 3;
        const int s = t & 7;
        const float* row = g_part[e];
        float a0 = 0, a1 = 0, a2 = 0, a3 = 0;
        for (int k = 0; k < 36; k += 4) {          // 296 = 8*37
            a0 += row[s + 8 * (k + 0)];
            a1 += row[s + 8 * (k + 1)];
            a2 += row[s + 8 * (k + 2)];
            a3 += row[s + 8 * (k + 3)];
        }
        a0 += row[s + 8 * 36];
        sp8[e][s] = (a0 + a1) + (a2 + a3);
    }
    __syncthreads();
    if (t < 65) {
        const float* r = sp8[t];
        s_acc[t] = ((r[0] + r[1]) + (r[2] + r[3])) + ((r[4] + r[5]) + (r[6] + r[7]));
    }
    __syncthreads();
    if (t >= 64) return;
    const int o = t;

    const int pidx[10] = {0, 1, 2, 3, 0, 1, 2, 0, 1, 2};
    const int aidx[10] = {-1, -1, -1, -1, 0, 1, 2, 3, 4, 5};

    double w[10];
#pragma unroll
    for (int cc = 0; cc < 10; cc++) w[cc] = (double)W[o * 10 + cc];
    const double NP = (double)NPIL * (double)PPTS;

    double mean = 0.0;
#pragma unroll
    for (int a = 0; a < 10; a++) {
        double g1 = (double)s_acc[pidx[a]];
        if (aidx[a] >= 0) g1 -= (double)s_acc[59 + aidx[a]];
        mean += w[a] * g1;
    }
    mean /= NP;

    double e2 = 0.0;
#pragma unroll
    for (int a = 0; a < 10; a++) {
#pragma unroll
        for (int b = 0; b < 10; b++) {
            if (b < a) continue;
            const int pa = pidx[a], pb = pidx[b];
            const int i4 = (pa <= pb) ? pa : pb;
            const int j4 = (pa <= pb) ? pb : pa;
            double g2 = (double)s_acc[4 + (i4 * 4 - i4 * (i4 - 1) / 2 + (j4 - i4))];
            if (aidx[a] >= 0) g2 -= (double)s_acc[14 + pb * 6 + aidx[a]];
            if (aidx[b] >= 0) g2 -= (double)s_acc[14 + pa * 6 + aidx[b]];
            if (aidx[a] >= 0 && aidx[b] >= 0) {
                const int i6 = (aidx[a] <= aidx[b]) ? aidx[a] : aidx[b];
                const int j6 = (aidx[a] <= aidx[b]) ? aidx[b] : aidx[a];
                g2 += (double)s_acc[38 + (i6 * 6 - i6 * (i6 - 1) / 2 + (j6 - i6))];
            }
            e2 += w[a] * w[b] * g2 * ((a == b) ? 1.0 : 2.0);
        }
    }
    e2 /= NP;

    const double var = e2 - mean * mean;
    const double aa = (double)gamma[o] / sqrt(var + 1e-3);
    const double bb = (double)beta[o] - mean * aa;
    float* p = g_params + o * 16;
    p[0]  = (float)(aa * (w[0] + w[4] + w[7]));
    p[1]  = (float)(aa * (w[1] + w[5] + w[8]));
    p[2]  = (float)(aa * (w[2] + w[6] + w[9]));
    p[3]  = (float)(aa * w[3]);
    p[4]  = (float)(aa * w[4]);
    p[5]  = (float)(aa * w[5]);
    p[6]  = (float)(aa * w[6]);
    p[7]  = (float)(aa * w[7]);
    p[8]  = (float)(aa * w[8]);
    p[9]  = (float)(aa * w[9]);
    p[10] = (float)bb;
    p[11] = 0.0f;
    p[12] = 0.0f; p[13] = 0.0f; p[14] = 0.0f; p[15] = 0.0f;
}

// ---------------------------------------------------------------------------
// k_out: warp = pillar. Inner nv-bounded max loop over shared tile;
// pb (pillar bias) computed AFTER the loop so pm/pc load latency is hidden;
// next pillar's q/nv prefetched. max_p(pb + d_p) == pb + max_p(d_p).
// ---------------------------------------------------------------------------
__global__ void __launch_bounds__(256) k_out(const float4* __restrict__ pts,
                                             const int* __restrict__ nvs,
                                             float* __restrict__ out) {
    __shared__ float4 sp[8][32];
    const int lane = threadIdx.x & 31;
    const int warp = threadIdx.x >> 5;
    const int gw = blockIdx.x * 8 + warp;
    const int nw = gridDim.x * 8;

    const float4* pp = (const float4*)g_params;
    const float4 wc0 = pp[lane * 4 + 0];
    const float4 m0v = pp[lane * 4 + 1];          // {aW4,aW5,aW6,aW7}
    const float4 t0v = pp[lane * 4 + 2];          // {aW8,aW9,b,pad}
    const float4 wc1 = pp[(lane + 32) * 4 + 0];
    const float4 m1v = pp[(lane + 32) * 4 + 1];
    const float4 t1v = pp[(lane + 32) * 4 + 2];

    int i = gw;
    if (i >= NPIL) return;
    float4 q = pts[i * PPTS + lane];
    int nv = nvs[i];

    for (;;) {
        sp[warp][lane] = q;
        const float4 pm = g_pm[2 * i];        // consumed after the loop
        const float4 pc = g_pm[2 * i + 1];
        __syncwarp();

        const int inext = i + nw;
        const bool more = inext < NPIL;
        float4 qn; int nvn = 0;
        if (more) {                            // prefetch next pillar
            qn = pts[inext * PPTS + lane];
            nvn = nvs[inext];
        }

        const float4* s4 = sp[warp];
        float a0 = -FLT_MAX, b0 = -FLT_MAX, a1 = -FLT_MAX, b1 = -FLT_MAX;
        int p = 0;
        for (; p + 2 <= nv; p += 2) {
            const float4 r0 = s4[p];
            const float4 r1 = s4[p + 1];
            a0 = fmaxf(a0, fmaf(r0.x, wc0.x, fmaf(r0.y, wc0.y, fmaf(r0.z, wc0.z, r0.w * wc0.w))));
            b0 = fmaxf(b0, fmaf(r1.x, wc0.x, fmaf(r1.y, wc0.y, fmaf(r1.z, wc0.z, r1.w * wc0.w))));
            a1 = fmaxf(a1, fmaf(r0.x, wc1.x, fmaf(r0.y, wc1.y, fmaf(r0.z, wc1.z, r0.w * wc1.w))));
            b1 = fmaxf(b1, fmaf(r1.x, wc1.x, fmaf(r1.y, wc1.y, fmaf(r1.z, wc1.z, r1.w * wc1.w))));
        }
        if (p < nv) {
            const float4 r0 = s4[p];
            a0 = fmaxf(a0, fmaf(r0.x, wc0.x, fmaf(r0.y, wc0.y, fmaf(r0.z, wc0.z, r0.w * wc0.w))));
            a1 = fmaxf(a1, fmaf(r0.x, wc1.x, fmaf(r0.y, wc1.y, fmaf(r0.z, wc1.z, r0.w * wc1.w))));
        }
        __syncwarp();

        const float pb0 = t0v.z - (pm.x * m0v.x + pm.y * m0v.y + pm.z * m0v.z)
                                - (pc.x * m0v.w + pc.y * t0v.x + pc.z * t0v.y);
        const float pb1 = t1v.z - (pm.x * m1v.x + pm.y * m1v.y + pm.z * m1v.z)
                                - (pc.x * m1v.w + pc.y * t1v.x + pc.z * t1v.y);

        float r0 = pb0 + fmaxf(a0, b0);
        float r1 = pb1 + fmaxf(a1, b1);
        if (nv < PPTS) {   // masked points contribute exactly b pre-ReLU
            r0 = fmaxf(r0, t0v.z);
            r1 = fmaxf(r1, t1v.z);
        }
        out[i * 64 + lane]      = fmaxf(r0, 0.0f);
        out[i * 64 + 32 + lane] = fmaxf(r1, 0.0f);

        if (!more) break;
        i = inext; q = qn; nv = nvn;
    }
}

extern "C" void kernel_launch(void* const* d_in, const int* in_sizes, int n_in,
                              void* d_out, int out_size) {
    const float4* feats  = (const float4*)d_in[0];
    const int*    nvs    = (const int*)d_in[1];
    const int4*   coords = (const int4*)d_in[2];
    const float*  W      = (const float*)d_in[3];
    const float*  gamma  = (const float*)d_in[4];
    const float*  beta   = (const float*)d_in[5];
    float* out = (float*)d_out;

    k_stats<<<SBLK, 256>>>(feats, nvs, coords);
    k_bn<<<1, 544>>>(W, gamma, beta);
    k_out<<<1184, 256>>>(feats, nvs, out);
}

// round 9
// speedup vs baseline: 1.4138x; 1.1071x over previous
#include <cuda_runtime.h>
#include <math.h>
#include <float.h>

#define NPIL 60000
#define PPTS 32
#define SBLK 592   // 4 blocks/SM at 61 regs — occupancy no longer grid-capped

// moment partials, entry-major for coalesced reduction:
// entry t: [0..3]=M1(sum u), [4..13]=M2 tri4, [14..37]=X[i*6+j]=sum(u_i*alpha_j),
//          [38..58]=A2 tri6 (nv*alpha_a*alpha_b), [59..64]=A1 (nv*alpha_j)
static __device__ float g_part[65][SBLK];
// per-channel folded params, 16 floats each (4 float4s)
static __device__ float g_params[64 * 16];
// per-pillar mean + center: [2i]={mx,my,mz,-}, [2i+1]={cx,cy,cz,-}
static __device__ float4 g_pm[NPIL * 2];

// owned-entry space e in [0,55): e<4 -> M1[e]; e<28 -> X[e-4]; e<49 -> A2[e-28]; else A1[e-49]
// operand table index: 0..5 = alpha (mx,my,mz,cx,cy,cz), 6..9 = S (masked sum of u), 10 = 1.0
__device__ __forceinline__ void decode_entry(int e, int& ia, int& ib, int& use_nv) {
    if (e < 4)       { ia = 6 + e; ib = 10; use_nv = 0; }
    else if (e < 28) { const int k = e - 4; ia = 6 + k / 6; ib = k % 6; use_nv = 0; }
    else if (e < 49) { int k = e - 28; int a = 0;
                       while (k >= 6 - a) { k -= 6 - a; a++; }
                       ia = a; ib = a + k; use_nv = 1; }
    else             { ia = e - 49; ib = 10; use_nv = 1; }
}

// ---------------------------------------------------------------------------
// k_stats: ONE pass over pts. Per-lane accumulators: M2 only (10).
// M1/X/A2/A1 are warp-uniform per pillar -> lane-owned (2 entries per lane)
// via a shared 11-operand table. Also computes and stores g_pm.
// ---------------------------------------------------------------------------
__global__ void __launch_bounds__(256) k_stats(const float4* __restrict__ pts,
                                               const int* __restrict__ nvs,
                                               const int4* __restrict__ coords) {
    __shared__ float sT[8][12];    // operand table per warp (11 used)
    __shared__ float sM2[8][10];
    __shared__ float sE[8][55];
    const int lane = threadIdx.x & 31;
    const int warp = threadIdx.x >> 5;
    const int gw = blockIdx.x * 8 + warp;
    const int nw = SBLK * 8;

    int iaA, ibA, unvA; decode_entry(lane, iaA, ibA, unvA);
    int iaB = 0, ibB = 10, unvB = 0;
    const bool hasB = (lane < 23);                 // entries 32..54
    if (hasB) decode_entry(lane + 32, iaB, ibB, unvB);

    float M2[10];
#pragma unroll
    for (int k = 0; k < 10; k++) M2[k] = 0.0f;
    float accA = 0.0f, accB = 0.0f;

    int i = gw;                                    // gw < 4736 <= NPIL always
    float4 q = pts[i * PPTS + lane];
    int nv = nvs[i];
    int4 c = coords[i];

    for (;;) {
        const int inext = i + nw;
        const bool more = inext < NPIL;
        float4 qn; int nvn = 0; int4 cn;
        if (more) {                                // prefetch next pillar
            qn = pts[inext * PPTS + lane];
            nvn = nvs[inext];
            cn = coords[inext];
        }

        // unmasked xyz sum (reference sums all 32 points, divides by nv)
        float sx = q.x, sy = q.y, sz = q.z;
#pragma unroll
        for (int s = 16; s > 0; s >>= 1) {
            sx += __shfl_xor_sync(0xffffffffu, sx, s);
            sy += __shfl_xor_sync(0xffffffffu, sy, s);
            sz += __shfl_xor_sync(0xffffffffu, sz, s);
        }
        const float inv = 1.0f / (float)nv;
        const float mx = sx * inv, my = sy * inv, mz = sz * inv;
        const float cx = (float)c.w * 0.2f + 0.1f;
        const float cy = (float)c.z * 0.2f - 39.9f;
        const float cz = (float)c.y * 4.0f - 1.0f;
        if (lane == 0) {
            g_pm[2 * i]     = make_float4(mx, my, mz, 0.0f);
            g_pm[2 * i + 1] = make_float4(cx, cy, cz, 0.0f);
        }

        // masked u + masked 4-dim pillar sum S
        const float valid = (lane < nv) ? 1.0f : 0.0f;
        const float ux = q.x * valid, uy = q.y * valid, uz = q.z * valid, uw = q.w * valid;
        float Sx = ux, Sy = uy, Sz = uz, Sw = uw;
#pragma unroll
        for (int s = 16; s > 0; s >>= 1) {
            Sx += __shfl_xor_sync(0xffffffffu, Sx, s);
            Sy += __shfl_xor_sync(0xffffffffu, Sy, s);
            Sz += __shfl_xor_sync(0xffffffffu, Sz, s);
            Sw += __shfl_xor_sync(0xffffffffu, Sw, s);
        }

        // stage operand table {alpha(6), S(4), 1}
        float sv = 1.0f;
        if (lane == 0) sv = mx; else if (lane == 1) sv = my; else if (lane == 2) sv = mz;
        else if (lane == 3) sv = cx; else if (lane == 4) sv = cy; else if (lane == 5) sv = cz;
        else if (lane == 6) sv = Sx; else if (lane == 7) sv = Sy;
        else if (lane == 8) sv = Sz; else if (lane == 9) sv = Sw;
        if (lane < 11) sT[warp][lane] = sv;
        __syncwarp();

        const float nvf = (float)nv;
        {
            const float va = sT[warp][iaA];
            const float vb = sT[warp][ibA];
            accA = fmaf(va * vb, unvA ? nvf : 1.0f, accA);
        }
        if (hasB) {
            const float va = sT[warp][iaB];
            const float vb = sT[warp][ibB];
            accB = fmaf(va * vb, unvB ? nvf : 1.0f, accB);
        }
        __syncwarp();   // table reads complete before next pillar overwrites

        // M2 (per-lane point-level) — independent of the table
        M2[0] = fmaf(ux, ux, M2[0]); M2[1] = fmaf(ux, uy, M2[1]);
        M2[2] = fmaf(ux, uz, M2[2]); M2[3] = fmaf(ux, uw, M2[3]);
        M2[4] = fmaf(uy, uy, M2[4]); M2[5] = fmaf(uy, uz, M2[5]);
        M2[6] = fmaf(uy, uw, M2[6]); M2[7] = fmaf(uz, uz, M2[7]);
        M2[8] = fmaf(uz, uw, M2[8]); M2[9] = fmaf(uw, uw, M2[9]);

        if (!more) break;
        i = inext; q = qn; nv = nvn; c = cn;
    }

    // epilogue: reduce M2 across the warp, stage owned entries, block-reduce
#pragma unroll
    for (int k = 0; k < 10; k++) {
        float v = M2[k];
#pragma unroll
        for (int s = 16; s > 0; s >>= 1) v += __shfl_xor_sync(0xffffffffu, v, s);
        if (lane == 0) sM2[warp][k] = v;
    }
    sE[warp][lane] = accA;                // entries 0..31
    if (hasB) sE[warp][lane + 32] = accB; // entries 32..54
    __syncthreads();

    const int t = threadIdx.x;
    if (t < 65) {
        float s = 0.0f;
#pragma unroll
        for (int w = 0; w < 8; w++) {
            if (t < 4)       s += sE[w][t];        // M1
            else if (t < 14) s += sM2[w][t - 4];   // M2
            else             s += sE[w][t - 10];   // X / A2 / A1
        }
        g_part[t][blockIdx.x] = s;
    }
}

// ---------------------------------------------------------------------------
// k_bn: parallel reduce of g_part (8 threads per entry), then per-channel
// BN-folded param derivation in double precision.
// ---------------------------------------------------------------------------
__global__ void __launch_bounds__(544) k_bn(const float* __restrict__ W,
                                            const float* __restrict__ gamma,
                                            const float* __restrict__ beta) {
    __shared__ float sp8[65][8];
    __shared__ float s_acc[65];
    const int t = threadIdx.x;
    if (t < 520) {
        const int e = t >> 3;
        const int s = t & 7;
        const float* row = g_part[e];
        float a0 = 0, a1 = 0, a2 = 0, a3 = 0;
        for (int k = 0; k < 72; k += 4) {          // 592 = 8*74; 74 = 4*18 + 2
            a0 += row[s + 8 * (k + 0)];
            a1 += row[s + 8 * (k + 1)];
            a2 += row[s + 8 * (k + 2)];
            a3 += row[s + 8 * (k + 3)];
        }
        a0 += row[s + 8 * 72];
        a1 += row[s + 8 * 73];
        sp8[e][s] = (a0 + a1) + (a2 + a3);
    }
    __syncthreads();
    if (t < 65) {
        const float* r = sp8[t];
        s_acc[t] = ((r[0] + r[1]) + (r[2] + r[3])) + ((r[4] + r[5]) + (r[6] + r[7]));
    }
    __syncthreads();
    if (t >= 64) return;
    const int o = t;

    const int pidx[10] = {0, 1, 2, 3, 0, 1, 2, 0, 1, 2};
    const int aidx[10] = {-1, -1, -1, -1, 0, 1, 2, 3, 4, 5};

    double w[10];
#pragma unroll
    for (int cc = 0; cc < 10; cc++) w[cc] = (double)W[o * 10 + cc];
    const double NP = (double)NPIL * (double)PPTS;

    double mean = 0.0;
#pragma unroll
    for (int a = 0; a < 10; a++) {
        double g1 = (double)s_acc[pidx[a]];
        if (aidx[a] >= 0) g1 -= (double)s_acc[59 + aidx[a]];
        mean += w[a] * g1;
    }
    mean /= NP;

    double e2 = 0.0;
#pragma unroll
    for (int a = 0; a < 10; a++) {
#pragma unroll
        for (int b = 0; b < 10; b++) {
            if (b < a) continue;
            const int pa = pidx[a], pb = pidx[b];
            const int i4 = (pa <= pb) ? pa : pb;
            const int j4 = (pa <= pb) ? pb : pa;
            double g2 = (double)s_acc[4 + (i4 * 4 - i4 * (i4 - 1) / 2 + (j4 - i4))];
            if (aidx[a] >= 0) g2 -= (double)s_acc[14 + pb * 6 + aidx[a]];
            if (aidx[b] >= 0) g2 -= (double)s_acc[14 + pa * 6 + aidx[b]];
            if (aidx[a] >= 0 && aidx[b] >= 0) {
                const int i6 = (aidx[a] <= aidx[b]) ? aidx[a] : aidx[b];
                const int j6 = (aidx[a] <= aidx[b]) ? aidx[b] : aidx[a];
                g2 += (double)s_acc[38 + (i6 * 6 - i6 * (i6 - 1) / 2 + (j6 - i6))];
            }
            e2 += w[a] * w[b] * g2 * ((a == b) ? 1.0 : 2.0);
        }
    }
    e2 /= NP;

    const double var = e2 - mean * mean;
    const double aa = (double)gamma[o] / sqrt(var + 1e-3);
    const double bb = (double)beta[o] - mean * aa;
    float* p = g_params + o * 16;
    p[0]  = (float)(aa * (w[0] + w[4] + w[7]));
    p[1]  = (float)(aa * (w[1] + w[5] + w[8]));
    p[2]  = (float)(aa * (w[2] + w[6] + w[9]));
    p[3]  = (float)(aa * w[3]);
    p[4]  = (float)(aa * w[4]);
    p[5]  = (float)(aa * w[5]);
    p[6]  = (float)(aa * w[6]);
    p[7]  = (float)(aa * w[7]);
    p[8]  = (float)(aa * w[8]);
    p[9]  = (float)(aa * w[9]);
    p[10] = (float)bb;
    p[11] = 0.0f;
    p[12] = 0.0f; p[13] = 0.0f; p[14] = 0.0f; p[15] = 0.0f;
}

// ---------------------------------------------------------------------------
// k_out: warp = pillar. Inner nv-bounded max loop over shared tile;
// pb (pillar bias) computed AFTER the loop so pm/pc load latency is hidden;
// next pillar's q/nv prefetched. max_p(pb + d_p) == pb + max_p(d_p).
// ---------------------------------------------------------------------------
__global__ void __launch_bounds__(256) k_out(const float4* __restrict__ pts,
                                             const int* __restrict__ nvs,
                                             float* __restrict__ out) {
    __shared__ float4 sp[8][32];
    const int lane = threadIdx.x & 31;
    const int warp = threadIdx.x >> 5;
    const int gw = blockIdx.x * 8 + warp;
    const int nw = gridDim.x * 8;

    const float4* pp = (const float4*)g_params;
    const float4 wc0 = pp[lane * 4 + 0];
    const float4 m0v = pp[lane * 4 + 1];          // {aW4,aW5,aW6,aW7}
    const float4 t0v = pp[lane * 4 + 2];          // {aW8,aW9,b,pad}
    const float4 wc1 = pp[(lane + 32) * 4 + 0];
    const float4 m1v = pp[(lane + 32) * 4 + 1];
    const float4 t1v = pp[(lane + 32) * 4 + 2];

    int i = gw;
    if (i >= NPIL) return;
    float4 q = pts[i * PPTS + lane];
    int nv = nvs[i];

    for (;;) {
        sp[warp][lane] = q;
        const float4 pm = g_pm[2 * i];        // consumed after the loop
        const float4 pc = g_pm[2 * i + 1];
        __syncwarp();

        const int inext = i + nw;
        const bool more = inext < NPIL;
        float4 qn; int nvn = 0;
        if (more) {                            // prefetch next pillar
            qn = pts[inext * PPTS + lane];
            nvn = nvs[inext];
        }

        const float4* s4 = sp[warp];
        float a0 = -FLT_MAX, b0 = -FLT_MAX, a1 = -FLT_MAX, b1 = -FLT_MAX;
        int p = 0;
        for (; p + 2 <= nv; p += 2) {
            const float4 r0 = s4[p];
            const float4 r1 = s4[p + 1];
            a0 = fmaxf(a0, fmaf(r0.x, wc0.x, fmaf(r0.y, wc0.y, fmaf(r0.z, wc0.z, r0.w * wc0.w))));
            b0 = fmaxf(b0, fmaf(r1.x, wc0.x, fmaf(r1.y, wc0.y, fmaf(r1.z, wc0.z, r1.w * wc0.w))));
            a1 = fmaxf(a1, fmaf(r0.x, wc1.x, fmaf(r0.y, wc1.y, fmaf(r0.z, wc1.z, r0.w * wc1.w))));
            b1 = fmaxf(b1, fmaf(r1.x, wc1.x, fmaf(r1.y, wc1.y, fmaf(r1.z, wc1.z, r1.w * wc1.w))));
        }
        if (p < nv) {
            const float4 r0 = s4[p];
            a0 = fmaxf(a0, fmaf(r0.x, wc0.x, fmaf(r0.y, wc0.y, fmaf(r0.z, wc0.z, r0.w * wc0.w))));
            a1 = fmaxf(a1, fmaf(r0.x, wc1.x, fmaf(r0.y, wc1.y, fmaf(r0.z, wc1.z, r0.w * wc1.w))));
        }
        __syncwarp();

        const float pb0 = t0v.z - (pm.x * m0v.x + pm.y * m0v.y + pm.z * m0v.z)
                                - (pc.x * m0v.w + pc.y * t0v.x + pc.z * t0v.y);
        const float pb1 = t1v.z - (pm.x * m1v.x + pm.y * m1v.y + pm.z * m1v.z)
                                - (pc.x * m1v.w + pc.y * t1v.x + pc.z * t1v.y);

        float r0 = pb0 + fmaxf(a0, b0);
        float r1 = pb1 + fmaxf(a1, b1);
        if (nv < PPTS) {   // masked points contribute exactly b pre-ReLU
            r0 = fmaxf(r0, t0v.z);
            r1 = fmaxf(r1, t1v.z);
        }
        out[i * 64 + lane]      = fmaxf(r0, 0.0f);
        out[i * 64 + 32 + lane] = fmaxf(r1, 0.0f);

        if (!more) break;
        i = inext; q = qn; nv = nvn;
    }
}

extern "C" void kernel_launch(void* const* d_in, const int* in_sizes, int n_in,
                              void* d_out, int out_size) {
    const float4* feats  = (const float4*)d_in[0];
    const int*    nvs    = (const int*)d_in[1];
    const int4*   coords = (const int4*)d_in[2];
    const float*  W      = (const float*)d_in[3];
    const float*  gamma  = (const float*)d_in[4];
    const float*  beta   = (const float*)d_in[5];
    float* out = (float*)d_out;

    k_stats<<<SBLK, 256>>>(feats, nvs, coords);
    k_bn<<<1, 544>>>(W, gamma, beta);
    k_out<<<1184, 256>>>(feats, nvs, out);
}